// round 14
// baseline (speedup 1.0000x reference)
#include <cuda_runtime.h>
#include <cuda_fp16.h>
#include <cstdint>

// Problem constants: B=2, N=2048, D=1024, H=16, hd=64
#define SEQ   2048
#define DIM   1024
#define HEADS 16
#define HD    64
#define BATCH 2
#define MROWS (BATCH * SEQ)   // 4096

// ---------------- scratch (device globals; no allocation allowed) ----------
__device__ __half g_x [MROWS * DIM];      // x fp16, pair-permuted k-groups
__device__ __half g_wq[DIM * DIM];
__device__ __half g_wk[DIM * DIM];
__device__ __half g_wv[DIM * DIM];
__device__ __half g_wo[DIM * DIM];
__device__ __half g_q [BATCH * HEADS * SEQ * HD];   // [b,h,tok,hd-paired] fp16
__device__ __half g_k [BATCH * HEADS * SEQ * HD];   // [b,h,tok,hd-paired] fp16
__device__ __half g_v [BATCH * HEADS * HD * SEQ];   // [b,h,hd,tok-paired] fp16
__device__ __half g_ao[MROWS * DIM];                // [b*tok, d-paired] fp16

// ---------------- helpers ---------------------------------------------------
__device__ __forceinline__ int sigma8(int p) { return (p & 3) * 2 + (p >> 2); }

__device__ __forceinline__ void mma_f16(float c[4], const unsigned a[4],
                                        unsigned b0, unsigned b1) {
    asm volatile(
        "mma.sync.aligned.m16n8k16.row.col.f32.f16.f16.f32 "
        "{%0,%1,%2,%3}, {%4,%5,%6,%7}, {%8,%9}, {%0,%1,%2,%3};"
        : "+f"(c[0]), "+f"(c[1]), "+f"(c[2]), "+f"(c[3])
        : "r"(a[0]), "r"(a[1]), "r"(a[2]), "r"(a[3]), "r"(b0), "r"(b1));
}

__device__ __forceinline__ unsigned pack_f16(float lo, float hi) {
    unsigned r;
    asm("cvt.rn.f16x2.f32 %0, %1, %2;" : "=r"(r) : "f"(hi), "f"(lo));
    return r;
}

__device__ __forceinline__ unsigned ex2h2(unsigned h2) {
    unsigned r;
    asm("ex2.approx.f16x2 %0, %1;" : "=r"(r) : "r"(h2));
    return r;
}

__device__ __forceinline__ void cp16(void* s, const void* g) {
    unsigned sa = (unsigned)__cvta_generic_to_shared(s);
    asm volatile("cp.async.cg.shared.global [%0], [%1], 16;" :: "r"(sa), "l"(g));
}
#define CP_COMMIT asm volatile("cp.async.commit_group;")
#define CP_WAIT1  asm volatile("cp.async.wait_group 1;")

// ---------------- fp32 -> fp16 pair-permuted convert ------------------------
__device__ __forceinline__ void cvt_group(const float* src, __half* dst) {
    float v[16];
#pragma unroll
    for (int j = 0; j < 4; j++) {
        float4 a = *(const float4*)(src + j * 4);
        v[j*4] = a.x; v[j*4+1] = a.y; v[j*4+2] = a.z; v[j*4+3] = a.w;
    }
    __half2 h[8];
    h[0] = __floats2half2_rn(v[0],  v[1]);
    h[1] = __floats2half2_rn(v[8],  v[9]);
    h[2] = __floats2half2_rn(v[2],  v[3]);
    h[3] = __floats2half2_rn(v[10], v[11]);
    h[4] = __floats2half2_rn(v[4],  v[5]);
    h[5] = __floats2half2_rn(v[12], v[13]);
    h[6] = __floats2half2_rn(v[6],  v[7]);
    h[7] = __floats2half2_rn(v[14], v[15]);
    *(uint4*)(dst)     = *(uint4*)&h[0];
    *(uint4*)(dst + 8) = *(uint4*)&h[4];
}

__global__ __launch_bounds__(256) void cvt16(
    const float* __restrict__ src, __half* __restrict__ dst, int n)
{
    int i = (blockIdx.x * 256 + threadIdx.x) * 16;
    if (i >= n) return;
    cvt_group(src + i, dst + i);
}

__global__ __launch_bounds__(256) void cvt16w4(
    const float* __restrict__ s0, const float* __restrict__ s1,
    const float* __restrict__ s2, const float* __restrict__ s3,
    __half* __restrict__ d0, __half* __restrict__ d1,
    __half* __restrict__ d2, __half* __restrict__ d3, int n)
{
    const float* src; __half* dst;
    switch (blockIdx.y) {
        case 0: src = s0; dst = d0; break;
        case 1: src = s1; dst = d1; break;
        case 2: src = s2; dst = d2; break;
        default: src = s3; dst = d3; break;
    }
    int i = (blockIdx.x * 256 + threadIdx.x) * 16;
    if (i >= n) return;
    cvt_group(src + i, dst + i);
}

// ---------------- GEMM: C = (A @ W^T + bias) * scale  (fp16 k16 mma) --------
// CTA tile 128x256, 8 warps (2x4), warp tile 64x64 (4x8 mma tiles).
// K-tile 64 halves, 2-stage cp.async pipeline, 1 CTA/SM.
// mode 0: fp32 row-major. mode 1: Q/K paired scatter. mode 2: V [hd][tok-paired].
#define GST 40
#define GA_SZ (128 * GST)         // A stage words
#define GB_SZ (256 * GST)         // B stage words
#define GEMM_SMEM (2 * (GA_SZ + GB_SZ) * 4)   // 122880 B

__global__ __launch_bounds__(256, 1) void sgemm_f16(
    const __half* __restrict__ A,
    const __half* __restrict__ W0, const float* __restrict__ b0_, void* __restrict__ C0,
    int mode0, float scale0,
    const __half* __restrict__ W1, const float* __restrict__ b1_, void* __restrict__ C1,
    const __half* __restrict__ W2, const float* __restrict__ b2_, void* __restrict__ C2)
{
    const __half* W; const float* bias; void* C; int mode; float scale;
    if (blockIdx.z == 0)      { W = W0; bias = b0_; C = C0; mode = mode0; scale = scale0; }
    else if (blockIdx.z == 1) { W = W1; bias = b1_; C = C1; mode = 1;     scale = 1.f; }
    else                      { W = W2; bias = b2_; C = C2; mode = 2;     scale = 1.f; }

    extern __shared__ __align__(16) unsigned gsm[];
    unsigned* As = gsm;                      // [2][128*GST]
    unsigned* Ws = gsm + 2 * GA_SZ;          // [2][256*GST]

    const int t = threadIdx.x;
    const int w = t >> 5, lane = t & 31;
    const int g = lane >> 2, tid = lane & 3;
    const int m0 = blockIdx.y * 128, n0 = blockIdx.x * 256;
    const int wr = (w & 1) * 64;     // warp m offset (2 warps in m)
    const int wc = (w >> 1) * 64;    // warp n offset (4 warps in n)

    float acc[4][8][4];
#pragma unroll
    for (int mi = 0; mi < 4; mi++)
#pragma unroll
        for (int ni = 0; ni < 8; ni++)
#pragma unroll
            for (int e = 0; e < 4; e++) acc[mi][ni][e] = 0.f;

    // copy slots: A 128 rows x 8 chunks (2 thr/row, 4 chunks); B 256 rows x 8 (1 thr/row)
    const int acr = t >> 1, acc8 = (t & 1) * 4;

    auto load_tile = [&](int st, int k0) {
        unsigned* Ab = As + st * GA_SZ;
        unsigned* Wb = Ws + st * GB_SZ;
        const __half* ag = A + (long)(m0 + acr) * DIM + k0;
#pragma unroll
        for (int p = 0; p < 4; p++) {
            const int ch = acc8 + p;
            cp16(&Ab[acr * GST + ch * 4], ag + ch * 8);
        }
        const __half* wg = W + (long)(n0 + t) * DIM + k0;
#pragma unroll
        for (int ch = 0; ch < 8; ch++)
            cp16(&Wb[t * GST + ch * 4], wg + ch * 8);
    };

    load_tile(0, 0);
    CP_COMMIT;

    for (int kt = 0; kt < 16; kt++) {
        if (kt < 15) load_tile((kt + 1) & 1, (kt + 1) * 64);
        CP_COMMIT;
        CP_WAIT1;
        __syncthreads();

        const unsigned* Ab = As + (kt & 1) * GA_SZ;
        const unsigned* Wb = Ws + (kt & 1) * GB_SZ;
#pragma unroll
        for (int ks = 0; ks < 4; ks++) {
            const int wo = ks * 8 + 2 * tid;
            unsigned af[4][4], bf[8][2];
#pragma unroll
            for (int mi = 0; mi < 4; mi++) {
                const int rb = wr + mi * 16 + g;
                uint2 u0 = *(const uint2*)&Ab[rb * GST + wo];
                uint2 u1 = *(const uint2*)&Ab[(rb + 8) * GST + wo];
                af[mi][0] = u0.x; af[mi][2] = u0.y;
                af[mi][1] = u1.x; af[mi][3] = u1.y;
            }
#pragma unroll
            for (int ni = 0; ni < 8; ni++) {
                uint2 ub = *(const uint2*)&Wb[(wc + ni * 8 + g) * GST + wo];
                bf[ni][0] = ub.x; bf[ni][1] = ub.y;
            }
#pragma unroll
            for (int mi = 0; mi < 4; mi++)
#pragma unroll
                for (int ni = 0; ni < 8; ni++)
                    mma_f16(acc[mi][ni], af[mi], bf[ni][0], bf[ni][1]);
        }
        __syncthreads();
    }

    // epilogue
#pragma unroll
    for (int mi = 0; mi < 4; mi++) {
        const int r0 = m0 + wr + mi * 16 + g;
#pragma unroll
        for (int ni = 0; ni < 8; ni++) {
            const int c0 = n0 + wc + ni * 8 + tid * 2;
            const float b0 = bias[c0], b1 = bias[c0 + 1];
#pragma unroll
            for (int half_ = 0; half_ < 2; half_++) {
                const int r = r0 + half_ * 8;
                const float v0 = (acc[mi][ni][half_ * 2 + 0] + b0) * scale;
                const float v1 = (acc[mi][ni][half_ * 2 + 1] + b1) * scale;
                if (mode == 0) {
                    *(float2*)((float*)C + (long)r * DIM + c0) = make_float2(v0, v1);
                } else if (mode == 1) {
                    const int b = r >> 11, tok = r & 2047;
                    const int h = c0 >> 6, cc = c0 & 63;
                    const int p = (cc & 15) >> 1;
                    __half* dst = (__half*)C + (((long)(b * HEADS + h)) * SEQ + tok) * HD
                                  + (cc & ~15) + 2 * sigma8(p);
                    *(__half2*)dst = __floats2half2_rn(v0, v1);
                } else {
                    const int b = r >> 11, tok = r & 2047;
                    const int h = c0 >> 6, cc = c0 & 63;
                    const int pt = (tok & ~15) + 2 * sigma8((tok & 15) >> 1) + (tok & 1);
                    __half* dst = (__half*)C;
                    const long hb = ((long)(b * HEADS + h)) * HD;
                    dst[(hb + cc)     * SEQ + pt] = __float2half_rn(v0);
                    dst[(hb + cc + 1) * SEQ + pt] = __float2half_rn(v1);
                }
            }
        }
    }
}

// ---------------- Flash attention (fp16, cross-iteration pipelined) ---------
// QB=128, 256 threads. 3-slot K/V ring. Per iteration: pack P(kb) (frees s),
// then one fused mma burst: rowsum + PV(kb) + S(kb+1) (independent chains).
#define QB  128
#define KB  64
#define KSTW 40
#define VSTW 40
#define NSLOT 3
#define FA_SMEM (NSLOT * (KB * KSTW + KB * VSTW) * 4)   // 61440 B
#define ONES_H2 0x3C003C00u

__global__ __launch_bounds__(256, 2) void flash_f16(
    const __half* __restrict__ q, const __half* __restrict__ k,
    const __half* __restrict__ v, __half* __restrict__ ao)
{
    extern __shared__ __align__(16) unsigned fsm[];
    unsigned* Ks = fsm;                       // [3][64*KSTW]
    unsigned* Vs = fsm + NSLOT * KB * KSTW;   // [3][64*VSTW]

    const int t = threadIdx.x;
    const int w = t >> 5, lane = t & 31;
    const int g = lane >> 2, tid = lane & 3;
    const int qb = blockIdx.x, h = blockIdx.y, b = blockIdx.z;
    const int r0 = w * 16;

    const long base  = (long)(b * HEADS + h) * SEQ * HD;
    const long vbase = (long)(b * HEADS + h) * HD * SEQ;

    unsigned aq[4][4];
    {
        const __half* qr0 = q + base + (long)(qb * QB + r0 + g) * HD;
        const __half* qr1 = qr0 + 8 * HD;
#pragma unroll
        for (int ks = 0; ks < 4; ks++) {
            uint2 u0 = *(const uint2*)(qr0 + ks * 16 + 4 * tid);
            uint2 u1 = *(const uint2*)(qr1 + ks * 16 + 4 * tid);
            aq[ks][0] = u0.x; aq[ks][2] = u0.y;
            aq[ks][1] = u1.x; aq[ks][3] = u1.y;
        }
    }

    float o[8][4];
#pragma unroll
    for (int ni = 0; ni < 8; ni++)
#pragma unroll
        for (int e = 0; e < 4; e++) o[ni][e] = 0.f;
    float la[4] = {0.f, 0.f, 0.f, 0.f};

    const int cr = t >> 2, cc4 = t & 3;

    auto load_kv = [&](int st, int kb) {
        unsigned* Kb = Ks + st * KB * KSTW;
        unsigned* Vb = Vs + st * KB * VSTW;
        const __half* kg = k + base + (long)kb * KB * HD + (long)cr * HD;
        const __half* vg = v + vbase + (long)cr * SEQ + kb * KB;
#pragma unroll
        for (int p = 0; p < 2; p++) {
            const int ch = cc4 + p * 4;
            cp16(&Kb[cr * KSTW + ch * 4], kg + ch * 8);
            cp16(&Vb[cr * VSTW + ch * 4], vg + ch * 8);
        }
    };

    load_kv(0, 0); CP_COMMIT;
    load_kv(1, 1); CP_COMMIT;
    CP_WAIT1;
    __syncthreads();

    float s[8][4];
#pragma unroll
    for (int ni = 0; ni < 8; ni++)
#pragma unroll
        for (int e = 0; e < 4; e++) s[ni][e] = 0.f;
#pragma unroll
    for (int ks = 0; ks < 4; ks++) {
        const int wo = ks * 8 + 2 * tid;
#pragma unroll
        for (int ni = 0; ni < 8; ni++) {
            uint2 ub = *(const uint2*)&Ks[(ni * 8 + g) * KSTW + wo];
            mma_f16(s[ni], aq[ks], ub.x, ub.y);
        }
    }

    for (int kb = 0; kb < SEQ / KB; kb++) {
        __syncthreads();
        if (kb + 2 < SEQ / KB) load_kv((kb + 2) % NSLOT, kb + 2);
        CP_COMMIT;

        unsigned pa[4][4];
#pragma unroll
        for (int j = 0; j < 4; j++) {
            pa[j][0] = ex2h2(pack_f16(s[2*j][0],   s[2*j][1]));
            pa[j][1] = ex2h2(pack_f16(s[2*j][2],   s[2*j][3]));
            pa[j][2] = ex2h2(pack_f16(s[2*j+1][0], s[2*j+1][1]));
            pa[j][3] = ex2h2(pack_f16(s[2*j+1][2], s[2*j+1][3]));
        }
#pragma unroll
        for (int ni = 0; ni < 8; ni++)
#pragma unroll
            for (int e = 0; e < 4; e++) s[ni][e] = 0.f;

        CP_WAIT1;
        __syncthreads();

        const unsigned* Vc = Vs + (kb % NSLOT) * KB * VSTW;
        const unsigned* Kn = Ks + ((kb + 1) % NSLOT) * KB * KSTW;
        const bool more = (kb + 1 < SEQ / KB);

#pragma unroll
        for (int j = 0; j < 4; j++) {
            mma_f16(la, pa[j], ONES_H2, ONES_H2);
#pragma unroll
            for (int ni = 0; ni < 8; ni++) {
                uint2 vv = *(const uint2*)&Vc[(ni * 8 + g) * VSTW + 8 * j + 2 * tid];
                mma_f16(o[ni], pa[j], vv.x, vv.y);
            }
            if (more) {
                const int wo = j * 8 + 2 * tid;
#pragma unroll
                for (int ni = 0; ni < 8; ni++) {
                    uint2 ub = *(const uint2*)&Kn[(ni * 8 + g) * KSTW + wo];
                    mma_f16(s[ni], aq[j], ub.x, ub.y);
                }
            }
        }
    }

    const float inv0 = 1.f / la[0], inv1 = 1.f / la[2];
    const int tok0 = qb * QB + r0 + g;
    __half* dst0 = ao + ((long)(b * SEQ) + tok0) * DIM + h * HD;
    __half* dst1 = dst0 + 8 * DIM;
#pragma unroll
    for (int ni = 0; ni < 8; ni++) {
        const int cbase = (ni >> 1) * 16;
        const int p = (ni & 1) * 4 + tid;
        const int off = cbase + 2 * sigma8(p);
        *(__half2*)(dst0 + off) = __floats2half2_rn(o[ni][0] * inv0, o[ni][1] * inv0);
        *(__half2*)(dst1 + off) = __floats2half2_rn(o[ni][2] * inv1, o[ni][3] * inv1);
    }
}

// ---------------- launch ----------------------------------------------------
extern "C" void kernel_launch(void* const* d_in, const int* in_sizes, int n_in,
                              void* d_out, int out_size)
{
    const float* x  = (const float*)d_in[0];
    const float* Wq = (const float*)d_in[1];
    const float* bq = (const float*)d_in[2];
    const float* Wk = (const float*)d_in[3];
    const float* bk = (const float*)d_in[4];
    const float* Wv = (const float*)d_in[5];
    const float* bv = (const float*)d_in[6];
    const float* Wo = (const float*)d_in[7];
    const float* bo = (const float*)d_in[8];
    float* out = (float*)d_out;

    __half *gx, *gwq, *gwk, *gwv, *gwo, *gq, *gk, *gv, *gao;
    cudaGetSymbolAddress((void**)&gx,  g_x);
    cudaGetSymbolAddress((void**)&gwq, g_wq);
    cudaGetSymbolAddress((void**)&gwk, g_wk);
    cudaGetSymbolAddress((void**)&gwv, g_wv);
    cudaGetSymbolAddress((void**)&gwo, g_wo);
    cudaGetSymbolAddress((void**)&gq,  g_q);
    cudaGetSymbolAddress((void**)&gk,  g_k);
    cudaGetSymbolAddress((void**)&gv,  g_v);
    cudaGetSymbolAddress((void**)&gao, g_ao);

    cudaFuncSetAttribute(sgemm_f16,
                         cudaFuncAttributeMaxDynamicSharedMemorySize, GEMM_SMEM);
    cudaFuncSetAttribute(flash_f16,
                         cudaFuncAttributeMaxDynamicSharedMemorySize, FA_SMEM);

    const int NX = MROWS * DIM, NW = DIM * DIM;
    cvt16<<<NX / 4096, 256>>>(x, gx, NX);
    cvt16w4<<<dim3(NW / 4096, 4), 256>>>(Wq, Wk, Wv, Wo, gwq, gwk, gwv, gwo, NW);

    // scores in log2 domain: qscale = log2(e) / sqrt(1024)
    const float qscale = 1.44269504088896f * 0.03125f;

    sgemm_f16<<<dim3(DIM / 256, MROWS / 128, 3), 256, GEMM_SMEM>>>(
        gx, gwq, bq, gq, 1, qscale, gwk, bk, gk, gwv, bv, gv);

    flash_f16<<<dim3(SEQ / QB, HEADS, BATCH), 256, FA_SMEM>>>(gq, gk, gv, gao);

    sgemm_f16<<<dim3(DIM / 256, MROWS / 128, 1), 256, GEMM_SMEM>>>(
        gao, gwo, bo, out, 0, 1.f, gwo, bo, out, gwo, bo, out);
}

// round 16
// speedup vs baseline: 1.0486x; 1.0486x over previous
#include <cuda_runtime.h>
#include <cuda_fp16.h>
#include <cstdint>

// Problem constants: B=2, N=2048, D=1024, H=16, hd=64
#define SEQ   2048
#define DIM   1024
#define HEADS 16
#define HD    64
#define BATCH 2
#define MROWS (BATCH * SEQ)   // 4096

// ---------------- scratch (device globals; no allocation allowed) ----------
__device__ __half g_x [MROWS * DIM];      // x fp16, pair-permuted k-groups
__device__ __half g_wq[DIM * DIM];
__device__ __half g_wk[DIM * DIM];
__device__ __half g_wv[DIM * DIM];
__device__ __half g_wo[DIM * DIM];
__device__ __half g_q [BATCH * HEADS * SEQ * HD];   // [b,h,tok,hd-paired] fp16
__device__ __half g_k [BATCH * HEADS * SEQ * HD];   // [b,h,tok,hd-paired] fp16
__device__ __half g_v [BATCH * HEADS * HD * SEQ];   // [b,h,hd,tok-paired] fp16
__device__ __half g_ao[MROWS * DIM];                // [b*tok, d-paired] fp16

// ---------------- helpers ---------------------------------------------------
__device__ __forceinline__ int sigma8(int p) { return (p & 3) * 2 + (p >> 2); }

__device__ __forceinline__ void mma_f16(float c[4], const unsigned a[4],
                                        unsigned b0, unsigned b1) {
    asm volatile(
        "mma.sync.aligned.m16n8k16.row.col.f32.f16.f16.f32 "
        "{%0,%1,%2,%3}, {%4,%5,%6,%7}, {%8,%9}, {%0,%1,%2,%3};"
        : "+f"(c[0]), "+f"(c[1]), "+f"(c[2]), "+f"(c[3])
        : "r"(a[0]), "r"(a[1]), "r"(a[2]), "r"(a[3]), "r"(b0), "r"(b1));
}

__device__ __forceinline__ unsigned pack_f16(float lo, float hi) {
    unsigned r;
    asm("cvt.rn.f16x2.f32 %0, %1, %2;" : "=r"(r) : "f"(hi), "f"(lo));
    return r;
}

__device__ __forceinline__ unsigned ex2h2(unsigned h2) {
    unsigned r;
    asm("ex2.approx.f16x2 %0, %1;" : "=r"(r) : "r"(h2));
    return r;
}

__device__ __forceinline__ void cp16(void* s, const void* g) {
    unsigned sa = (unsigned)__cvta_generic_to_shared(s);
    asm volatile("cp.async.cg.shared.global [%0], [%1], 16;" :: "r"(sa), "l"(g));
}
#define CP_COMMIT asm volatile("cp.async.commit_group;")
#define CP_WAIT0  asm volatile("cp.async.wait_group 0;")
#define CP_WAIT1  asm volatile("cp.async.wait_group 1;")

// ---------------- fp32 -> fp16 pair-permuted convert ------------------------
__device__ __forceinline__ void cvt_group(const float* src, __half* dst) {
    float v[16];
#pragma unroll
    for (int j = 0; j < 4; j++) {
        float4 a = *(const float4*)(src + j * 4);
        v[j*4] = a.x; v[j*4+1] = a.y; v[j*4+2] = a.z; v[j*4+3] = a.w;
    }
    __half2 h[8];
    h[0] = __floats2half2_rn(v[0],  v[1]);
    h[1] = __floats2half2_rn(v[8],  v[9]);
    h[2] = __floats2half2_rn(v[2],  v[3]);
    h[3] = __floats2half2_rn(v[10], v[11]);
    h[4] = __floats2half2_rn(v[4],  v[5]);
    h[5] = __floats2half2_rn(v[12], v[13]);
    h[6] = __floats2half2_rn(v[6],  v[7]);
    h[7] = __floats2half2_rn(v[14], v[15]);
    *(uint4*)(dst)     = *(uint4*)&h[0];
    *(uint4*)(dst + 8) = *(uint4*)&h[4];
}

__global__ __launch_bounds__(256) void cvt16(
    const float* __restrict__ src, __half* __restrict__ dst, int n)
{
    int i = (blockIdx.x * 256 + threadIdx.x) * 16;
    if (i >= n) return;
    cvt_group(src + i, dst + i);
}

__global__ __launch_bounds__(256) void cvt16w4(
    const float* __restrict__ s0, const float* __restrict__ s1,
    const float* __restrict__ s2, const float* __restrict__ s3,
    __half* __restrict__ d0, __half* __restrict__ d1,
    __half* __restrict__ d2, __half* __restrict__ d3, int n)
{
    const float* src; __half* dst;
    switch (blockIdx.y) {
        case 0: src = s0; dst = d0; break;
        case 1: src = s1; dst = d1; break;
        case 2: src = s2; dst = d2; break;
        default: src = s3; dst = d3; break;
    }
    int i = (blockIdx.x * 256 + threadIdx.x) * 16;
    if (i >= n) return;
    cvt_group(src + i, dst + i);
}

// ---------------- GEMM: C = (A @ W^T + bias) * scale  (fp16 k16 mma) --------
// R10 tile shape (128x128 CTA, 64x32 warp tile) with SINGLE-barrier pipeline:
// per k-tile: wait(all) -> sync -> issue loads(kt+1) -> compute(kt).
// mode 0: fp32 row-major. mode 1: Q/K paired scatter. mode 2: V [hd][tok-paired].
#define GST 40
#define GEMM_SMEM (2 * 2 * 128 * GST * 4)   // 81920 B

__global__ __launch_bounds__(256, 2) void sgemm_f16(
    const __half* __restrict__ A,
    const __half* __restrict__ W0, const float* __restrict__ b0_, void* __restrict__ C0,
    int mode0, float scale0,
    const __half* __restrict__ W1, const float* __restrict__ b1_, void* __restrict__ C1,
    const __half* __restrict__ W2, const float* __restrict__ b2_, void* __restrict__ C2)
{
    const __half* W; const float* bias; void* C; int mode; float scale;
    if (blockIdx.z == 0)      { W = W0; bias = b0_; C = C0; mode = mode0; scale = scale0; }
    else if (blockIdx.z == 1) { W = W1; bias = b1_; C = C1; mode = 1;     scale = 1.f; }
    else                      { W = W2; bias = b2_; C = C2; mode = 2;     scale = 1.f; }

    extern __shared__ __align__(16) unsigned gsm[];
    unsigned* As = gsm;                    // [2][128*GST]
    unsigned* Ws = gsm + 2 * 128 * GST;

    const int t = threadIdx.x;
    const int w = t >> 5, lane = t & 31;
    const int g = lane >> 2, tid = lane & 3;
    const int m0 = blockIdx.y * 128, n0 = blockIdx.x * 128;
    const int wr = (w >> 2) * 64;
    const int wc = (w & 3) * 32;

    float acc[4][4][4];
#pragma unroll
    for (int mi = 0; mi < 4; mi++)
#pragma unroll
        for (int ni = 0; ni < 4; ni++)
#pragma unroll
            for (int e = 0; e < 4; e++) acc[mi][ni][e] = 0.f;

    const int cr = t >> 1, cc8 = (t & 1) * 4;

    auto load_tile = [&](int st, int k0) {
        unsigned* Ab = As + st * 128 * GST;
        unsigned* Wb = Ws + st * 128 * GST;
        const __half* ag = A + (long)(m0 + cr) * DIM + k0;
        const __half* wg = W + (long)(n0 + cr) * DIM + k0;
#pragma unroll
        for (int p = 0; p < 4; p++) {
            const int ch = cc8 + p;
            cp16(&Ab[cr * GST + ch * 4], ag + ch * 8);
            cp16(&Wb[cr * GST + ch * 4], wg + ch * 8);
        }
    };

    load_tile(0, 0);
    CP_COMMIT;

    for (int kt = 0; kt < 16; kt++) {
        CP_WAIT0;            // loads(kt) (own groups) done
        __syncthreads();     // loads(kt) globally visible; all warps past compute(kt-1)
        if (kt < 15) {       // issue loads(kt+1) into the buffer compute(kt-1) used
            load_tile((kt + 1) & 1, (kt + 1) * 64);
            CP_COMMIT;
        }

        const unsigned* Ab = As + (kt & 1) * 128 * GST;
        const unsigned* Wb = Ws + (kt & 1) * 128 * GST;
#pragma unroll
        for (int ks = 0; ks < 4; ks++) {
            const int wo = ks * 8 + 2 * tid;
            unsigned af[4][4], bf[4][2];
#pragma unroll
            for (int mi = 0; mi < 4; mi++) {
                const int rb = wr + mi * 16 + g;
                uint2 u0 = *(const uint2*)&Ab[rb * GST + wo];
                uint2 u1 = *(const uint2*)&Ab[(rb + 8) * GST + wo];
                af[mi][0] = u0.x; af[mi][2] = u0.y;
                af[mi][1] = u1.x; af[mi][3] = u1.y;
            }
#pragma unroll
            for (int ni = 0; ni < 4; ni++) {
                uint2 ub = *(const uint2*)&Wb[(wc + ni * 8 + g) * GST + wo];
                bf[ni][0] = ub.x; bf[ni][1] = ub.y;
            }
#pragma unroll
            for (int mi = 0; mi < 4; mi++)
#pragma unroll
                for (int ni = 0; ni < 4; ni++)
                    mma_f16(acc[mi][ni], af[mi], bf[ni][0], bf[ni][1]);
        }
    }

    // epilogue
#pragma unroll
    for (int mi = 0; mi < 4; mi++) {
        const int r0 = m0 + wr + mi * 16 + g;
#pragma unroll
        for (int ni = 0; ni < 4; ni++) {
            const int c0 = n0 + wc + ni * 8 + tid * 2;
            const float b0 = bias[c0], b1 = bias[c0 + 1];
#pragma unroll
            for (int half_ = 0; half_ < 2; half_++) {
                const int r = r0 + half_ * 8;
                const float v0 = (acc[mi][ni][half_ * 2 + 0] + b0) * scale;
                const float v1 = (acc[mi][ni][half_ * 2 + 1] + b1) * scale;
                if (mode == 0) {
                    *(float2*)((float*)C + (long)r * DIM + c0) = make_float2(v0, v1);
                } else if (mode == 1) {
                    const int b = r >> 11, tok = r & 2047;
                    const int h = c0 >> 6, cc = c0 & 63;
                    const int p = (cc & 15) >> 1;
                    __half* dst = (__half*)C + (((long)(b * HEADS + h)) * SEQ + tok) * HD
                                  + (cc & ~15) + 2 * sigma8(p);
                    *(__half2*)dst = __floats2half2_rn(v0, v1);
                } else {
                    const int b = r >> 11, tok = r & 2047;
                    const int h = c0 >> 6, cc = c0 & 63;
                    const int pt = (tok & ~15) + 2 * sigma8((tok & 15) >> 1) + (tok & 1);
                    __half* dst = (__half*)C;
                    const long hb = ((long)(b * HEADS + h)) * HD;
                    dst[(hb + cc)     * SEQ + pt] = __float2half_rn(v0);
                    dst[(hb + cc + 1) * SEQ + pt] = __float2half_rn(v1);
                }
            }
        }
    }
}

// ---------------- Flash attention (fp16, cross-iteration pipelined) ---------
// QB=128, 256 threads, 3-slot K/V ring, SINGLE barrier per k-block:
// wait(load kb+1) -> sync -> issue load(kb+2) -> pack P(kb) -> fused burst.
#define QB  128
#define KB  64
#define KSTW 40
#define VSTW 40
#define NSLOT 3
#define FA_SMEM (NSLOT * (KB * KSTW + KB * VSTW) * 4)   // 61440 B
#define ONES_H2 0x3C003C00u

__global__ __launch_bounds__(256, 2) void flash_f16(
    const __half* __restrict__ q, const __half* __restrict__ k,
    const __half* __restrict__ v, __half* __restrict__ ao)
{
    extern __shared__ __align__(16) unsigned fsm[];
    unsigned* Ks = fsm;                       // [3][64*KSTW]
    unsigned* Vs = fsm + NSLOT * KB * KSTW;   // [3][64*VSTW]

    const int t = threadIdx.x;
    const int w = t >> 5, lane = t & 31;
    const int g = lane >> 2, tid = lane & 3;
    const int qb = blockIdx.x, h = blockIdx.y, b = blockIdx.z;
    const int r0 = w * 16;

    const long base  = (long)(b * HEADS + h) * SEQ * HD;
    const long vbase = (long)(b * HEADS + h) * HD * SEQ;

    // Q fragments in registers (gmem fp16 pair-permuted)
    unsigned aq[4][4];
    {
        const __half* qr0 = q + base + (long)(qb * QB + r0 + g) * HD;
        const __half* qr1 = qr0 + 8 * HD;
#pragma unroll
        for (int ks = 0; ks < 4; ks++) {
            uint2 u0 = *(const uint2*)(qr0 + ks * 16 + 4 * tid);
            uint2 u1 = *(const uint2*)(qr1 + ks * 16 + 4 * tid);
            aq[ks][0] = u0.x; aq[ks][2] = u0.y;
            aq[ks][1] = u1.x; aq[ks][3] = u1.y;
        }
    }

    float o[8][4];
#pragma unroll
    for (int ni = 0; ni < 8; ni++)
#pragma unroll
        for (int e = 0; e < 4; e++) o[ni][e] = 0.f;
    float la[4] = {0.f, 0.f, 0.f, 0.f};

    const int cr = t >> 2, cc4 = t & 3;

    auto load_kv = [&](int st, int kb) {
        unsigned* Kb = Ks + st * KB * KSTW;
        unsigned* Vb = Vs + st * KB * VSTW;
        const __half* kg = k + base + (long)kb * KB * HD + (long)cr * HD;
        const __half* vg = v + vbase + (long)cr * SEQ + kb * KB;
#pragma unroll
        for (int p = 0; p < 2; p++) {
            const int ch = cc4 + p * 4;
            cp16(&Kb[cr * KSTW + ch * 4], kg + ch * 8);
            cp16(&Vb[cr * VSTW + ch * 4], vg + ch * 8);
        }
    };

    // prologue: slots 0,1 in flight; S(0) once slot 0 lands
    load_kv(0, 0); CP_COMMIT;
    load_kv(1, 1); CP_COMMIT;
    CP_WAIT1;
    __syncthreads();

    float s[8][4];
#pragma unroll
    for (int ni = 0; ni < 8; ni++)
#pragma unroll
        for (int e = 0; e < 4; e++) s[ni][e] = 0.f;
#pragma unroll
    for (int ks = 0; ks < 4; ks++) {
        const int wo = ks * 8 + 2 * tid;
#pragma unroll
        for (int ni = 0; ni < 8; ni++) {
            uint2 ub = *(const uint2*)&Ks[(ni * 8 + g) * KSTW + wo];
            mma_f16(s[ni], aq[ks], ub.x, ub.y);
        }
    }

    for (int kb = 0; kb < SEQ / KB; kb++) {
        CP_WAIT0;            // K/V(kb+1) (own groups) done
        __syncthreads();     // visible to all; all warps past burst(kb-1)
        if (kb + 2 < SEQ / KB) {   // slot (kb+2)%3 was last read by burst(kb-1)
            load_kv((kb + 2) % NSLOT, kb + 2);
            CP_COMMIT;
        }

        // softmax: pack P(kb) (frees s), zero s for S(kb+1)
        unsigned pa[4][4];
#pragma unroll
        for (int j = 0; j < 4; j++) {
            pa[j][0] = ex2h2(pack_f16(s[2*j][0],   s[2*j][1]));
            pa[j][1] = ex2h2(pack_f16(s[2*j][2],   s[2*j][3]));
            pa[j][2] = ex2h2(pack_f16(s[2*j+1][0], s[2*j+1][1]));
            pa[j][3] = ex2h2(pack_f16(s[2*j+1][2], s[2*j+1][3]));
        }
#pragma unroll
        for (int ni = 0; ni < 8; ni++)
#pragma unroll
            for (int e = 0; e < 4; e++) s[ni][e] = 0.f;

        const unsigned* Vc = Vs + (kb % NSLOT) * KB * VSTW;
        const unsigned* Kn = Ks + ((kb + 1) % NSLOT) * KB * KSTW;
        const bool more = (kb + 1 < SEQ / KB);

        // fused burst: rowsum + PV(kb) + S(kb+1); independent chains per j
#pragma unroll
        for (int j = 0; j < 4; j++) {
            mma_f16(la, pa[j], ONES_H2, ONES_H2);
#pragma unroll
            for (int ni = 0; ni < 8; ni++) {
                uint2 vv = *(const uint2*)&Vc[(ni * 8 + g) * VSTW + 8 * j + 2 * tid];
                mma_f16(o[ni], pa[j], vv.x, vv.y);
            }
            if (more) {
                const int wo = j * 8 + 2 * tid;
#pragma unroll
                for (int ni = 0; ni < 8; ni++) {
                    uint2 ub = *(const uint2*)&Kn[(ni * 8 + g) * KSTW + wo];
                    mma_f16(s[ni], aq[j], ub.x, ub.y);
                }
            }
        }
    }

    // epilogue -> fp16 pair-permuted [b*tok, d] (feeds O-proj)
    const float inv0 = 1.f / la[0], inv1 = 1.f / la[2];
    const int tok0 = qb * QB + r0 + g;
    __half* dst0 = ao + ((long)(b * SEQ) + tok0) * DIM + h * HD;
    __half* dst1 = dst0 + 8 * DIM;
#pragma unroll
    for (int ni = 0; ni < 8; ni++) {
        const int cbase = (ni >> 1) * 16;
        const int p = (ni & 1) * 4 + tid;
        const int off = cbase + 2 * sigma8(p);
        *(__half2*)(dst0 + off) = __floats2half2_rn(o[ni][0] * inv0, o[ni][1] * inv0);
        *(__half2*)(dst1 + off) = __floats2half2_rn(o[ni][2] * inv1, o[ni][3] * inv1);
    }
}

// ---------------- launch ----------------------------------------------------
extern "C" void kernel_launch(void* const* d_in, const int* in_sizes, int n_in,
                              void* d_out, int out_size)
{
    const float* x  = (const float*)d_in[0];
    const float* Wq = (const float*)d_in[1];
    const float* bq = (const float*)d_in[2];
    const float* Wk = (const float*)d_in[3];
    const float* bk = (const float*)d_in[4];
    const float* Wv = (const float*)d_in[5];
    const float* bv = (const float*)d_in[6];
    const float* Wo = (const float*)d_in[7];
    const float* bo = (const float*)d_in[8];
    float* out = (float*)d_out;

    __half *gx, *gwq, *gwk, *gwv, *gwo, *gq, *gk, *gv, *gao;
    cudaGetSymbolAddress((void**)&gx,  g_x);
    cudaGetSymbolAddress((void**)&gwq, g_wq);
    cudaGetSymbolAddress((void**)&gwk, g_wk);
    cudaGetSymbolAddress((void**)&gwv, g_wv);
    cudaGetSymbolAddress((void**)&gwo, g_wo);
    cudaGetSymbolAddress((void**)&gq,  g_q);
    cudaGetSymbolAddress((void**)&gk,  g_k);
    cudaGetSymbolAddress((void**)&gv,  g_v);
    cudaGetSymbolAddress((void**)&gao, g_ao);

    cudaFuncSetAttribute(sgemm_f16,
                         cudaFuncAttributeMaxDynamicSharedMemorySize, GEMM_SMEM);
    cudaFuncSetAttribute(flash_f16,
                         cudaFuncAttributeMaxDynamicSharedMemorySize, FA_SMEM);

    const int NX = MROWS * DIM, NW = DIM * DIM;
    cvt16<<<NX / 4096, 256>>>(x, gx, NX);
    cvt16w4<<<dim3(NW / 4096, 4), 256>>>(Wq, Wk, Wv, Wo, gwq, gwk, gwv, gwo, NW);

    // scores in log2 domain: qscale = log2(e) / sqrt(1024)
    const float qscale = 1.44269504088896f * 0.03125f;

    sgemm_f16<<<dim3(DIM / 128, MROWS / 128, 3), 256, GEMM_SMEM>>>(
        gx, gwq, bq, gq, 1, qscale, gwk, bk, gk, gwv, bv, gv);

    flash_f16<<<dim3(SEQ / QB, HEADS, BATCH), 256, FA_SMEM>>>(gq, gk, gv, gao);

    sgemm_f16<<<dim3(DIM / 128, MROWS / 128, 1), 256, GEMM_SMEM>>>(
        gao, gwo, bo, out, 0, 1.f, gwo, bo, out, gwo, bo, out);
}